// round 3
// baseline (speedup 1.0000x reference)
#include <cuda_runtime.h>
#include <math.h>
#include <stdint.h>

#define HW 4096
#define EPSBN 1e-5f

// ---------------- scratch (static device allocations) ----------------
__device__ float d_wall[192 * 256];                 // folded W for convs 1,2,3 stacked
__device__ float d_ball[192];
__device__ float d_w4f[256 * 128];                  // folded W4
__device__ float d_b4f[256];
__device__ float d_yall[(size_t)8 * 192 * 4096];    // conv1/2/3 outputs (ReLU'd): rows 0-31 fpre, 32-63 g, 64-191 hpre
__device__ float d_fp[(size_t)8 * 32 * 1024];       // pooled f  [b][k][n]
__device__ float d_hp[(size_t)8 * 128 * 1024];      // pooled hh [b][c][n]
__device__ float d_ov[(size_t)8 * 128 * 4096];      // attention output o [b][c][m]

// ---------------- prep: fold BN into conv weights ----------------
__global__ void prep_kernel(
    const float* w1, const float* b1, const float* s1, const float* t1, const float* m1, const float* v1,
    const float* w2, const float* b2, const float* s2, const float* t2, const float* m2, const float* v2,
    const float* w3, const float* b3, const float* s3, const float* t3, const float* m3, const float* v3,
    const float* w4, const float* b4, const float* s4, const float* t4, const float* m4, const float* v4)
{
    int i = blockIdx.x * 256 + threadIdx.x;
    if (i < 192 * 256) {
        int row = i >> 8, c = i & 255;
        const float *w, *s, *v; int oc;
        if (row < 32)      { w = w1; s = s1; v = v1; oc = row; }
        else if (row < 64) { w = w2; s = s2; v = v2; oc = row - 32; }
        else               { w = w3; s = s3; v = v3; oc = row - 64; }
        float sc = s[oc] * rsqrtf(v[oc] + EPSBN);
        d_wall[i] = w[oc * 256 + c] * sc;
    }
    if (i < 256 * 128) {
        int row = i >> 7, c = i & 127;
        float sc = s4[row] * rsqrtf(v4[row] + EPSBN);
        d_w4f[i] = w4[row * 128 + c] * sc;
    }
    if (i < 192) {
        const float *bb, *s, *v, *mm, *tt; int oc;
        if (i < 32)      { bb = b1; s = s1; v = v1; mm = m1; tt = t1; oc = i; }
        else if (i < 64) { bb = b2; s = s2; v = v2; mm = m2; tt = t2; oc = i - 32; }
        else             { bb = b3; s = s3; v = v3; mm = m3; tt = t3; oc = i - 64; }
        float sc = s[oc] * rsqrtf(v[oc] + EPSBN);
        d_ball[i] = (bb[oc] - mm[oc]) * sc + tt[oc];
    }
    if (i < 256) {
        float sc = s4[i] * rsqrtf(v4[i] + EPSBN);
        d_b4f[i] = (b4[i] - m4[i]) * sc + t4[i];
    }
}

// ---------------- conv1x1 GEMM (MODE 0: convs1-3 + ReLU -> d_yall,
//                                MODE 1: conv4 + gamma*(.)+x -> out) ----------------
template <int MODE>
__global__ void gemm_kernel(const float* __restrict__ X, float* __restrict__ Out,
                            const float* __restrict__ gamma_p)
{
    constexpr int M = (MODE == 0) ? 192 : 256;
    constexpr int K = (MODE == 0) ? 256 : 128;
    const float* W    = (MODE == 0) ? d_wall : d_w4f;
    const float* bias = (MODE == 0) ? d_ball : d_b4f;

    const int b  = blockIdx.z;
    const int m0 = blockIdx.y * 64;
    const int n0 = blockIdx.x * 128;
    const float* in = ((MODE == 0) ? X : (const float*)d_ov) + (size_t)b * K * HW;
    float* Obase = (MODE == 0) ? d_yall : Out;

    __shared__ float ws[32][65];
    __shared__ float xs[32][128];

    float acc[4][8];
#pragma unroll
    for (int i = 0; i < 4; i++)
#pragma unroll
        for (int j = 0; j < 8; j++) acc[i][j] = 0.f;

    const int t = threadIdx.x;
    const int ty = t >> 4, tx = t & 15;

    for (int k0 = 0; k0 < K; k0 += 32) {
#pragma unroll
        for (int i = 0; i < 8; i++) {
            int e = t + i * 256; int mm = e >> 5, kk = e & 31;
            ws[kk][mm] = W[(m0 + mm) * K + k0 + kk];
        }
#pragma unroll
        for (int i = 0; i < 16; i++) {
            int e = t + i * 256; int kk = e >> 7, pp = e & 127;
            xs[kk][pp] = in[(size_t)(k0 + kk) * HW + n0 + pp];
        }
        __syncthreads();
#pragma unroll
        for (int kk = 0; kk < 32; kk++) {
            float wr[4], xr[8];
#pragma unroll
            for (int i = 0; i < 4; i++) wr[i] = ws[kk][ty * 4 + i];
#pragma unroll
            for (int j = 0; j < 8; j++) xr[j] = xs[kk][tx * 8 + j];
#pragma unroll
            for (int i = 0; i < 4; i++)
#pragma unroll
                for (int j = 0; j < 8; j++) acc[i][j] += wr[i] * xr[j];
        }
        __syncthreads();
    }

    float gm = (MODE == 1) ? gamma_p[0] : 0.f;
#pragma unroll
    for (int i = 0; i < 4; i++) {
        int r = m0 + ty * 4 + i;
        float bv = bias[r];
        size_t off = ((size_t)b * M + r) * HW + n0 + tx * 8;
        float4 o0, o1;
        if (MODE == 0) {
            o0.x = fmaxf(acc[i][0] + bv, 0.f); o0.y = fmaxf(acc[i][1] + bv, 0.f);
            o0.z = fmaxf(acc[i][2] + bv, 0.f); o0.w = fmaxf(acc[i][3] + bv, 0.f);
            o1.x = fmaxf(acc[i][4] + bv, 0.f); o1.y = fmaxf(acc[i][5] + bv, 0.f);
            o1.z = fmaxf(acc[i][6] + bv, 0.f); o1.w = fmaxf(acc[i][7] + bv, 0.f);
        } else {
            const float4 r0 = *(const float4*)(X + off);
            const float4 r1 = *(const float4*)(X + off + 4);
            o0.x = gm * (acc[i][0] + bv) + r0.x; o0.y = gm * (acc[i][1] + bv) + r0.y;
            o0.z = gm * (acc[i][2] + bv) + r0.z; o0.w = gm * (acc[i][3] + bv) + r0.w;
            o1.x = gm * (acc[i][4] + bv) + r1.x; o1.y = gm * (acc[i][5] + bv) + r1.y;
            o1.z = gm * (acc[i][6] + bv) + r1.z; o1.w = gm * (acc[i][7] + bv) + r1.w;
        }
        *(float4*)(Obase + off)     = o0;
        *(float4*)(Obase + off + 4) = o1;
    }
}

// ---------------- 2x2 maxpool on fpre and hpre ----------------
__global__ void pool_kernel()
{
    int idx = blockIdx.x * 256 + threadIdx.x;
    if (idx >= 8 * 160 * 1024) return;
    int n = idx & 1023;
    int r = (idx >> 10) % 160;
    int b = idx / (160 * 1024);
    int ph = n >> 5, pw = n & 31;
    int sr = (r < 32) ? r : r + 32;   // hpre rows live at 64..191
    const float* base = d_yall + ((size_t)(b * 192 + sr)) * HW + ph * 128 + pw * 2;
    float v = fmaxf(fmaxf(base[0], base[1]), fmaxf(base[64], base[65]));
    if (r < 32) d_fp[((size_t)b * 32 + r) * 1024 + n] = v;
    else        d_hp[((size_t)b * 128 + (r - 32)) * 1024 + n] = v;
}

// ---------------- fused flash-style attention ----------------
// logits S[n][m] = sum_k f[n][k]*g[k][m]; softmax over n (1024); o[c][m] = sum_n hh[c][n] P[n][m]
#define PADF 132
#define PADV 132
#define PADP 68

__global__ void attn_kernel()
{
    extern __shared__ float sm[];
    float* sg    = sm;                    // [32][64]   queries g
    float* sf    = sg + 32 * 64;          // [32][PADF] keys f (k-major)
    float* sv    = sf + 32 * PADF;        // [128][PADV] values v[n][c]
    float* sp    = sv + 128 * PADV;       // [128][PADP] logits/probs
    float* sred  = sp + 128 * PADP;       // [8][64] max then sum partials
    float* scorr = sred + 512;            // [64]
    float* sl    = scorr + 64;            // [64]

    const int b  = blockIdx.y;
    const int m0 = blockIdx.x * 64;
    const int t  = threadIdx.x;

    // q tile: sg[k][m] = g[b][k][m0+m]  (g = yall rows 32..63)
#pragma unroll
    for (int i = 0; i < 8; i++) {
        int e = t + i * 256; int k = e >> 6, mm = e & 63;
        sg[k * 64 + mm] = d_yall[((size_t)(b * 192 + 32 + k)) * HW + m0 + mm];
    }

    const int tyc = t >> 3, txm = t & 7;    // GEMM mapping: 32x8 threads, 4x8 register tile
    const int msm = t & 63, q = t >> 6;     // softmax mapping: 4 threads per query column

    float accO[4][8];
#pragma unroll
    for (int i = 0; i < 4; i++)
#pragma unroll
        for (int j = 0; j < 8; j++) accO[i][j] = 0.f;
    float runM = -3.0e38f, runL = 0.f;

    for (int n0 = 0; n0 < 1024; n0 += 128) {
        __syncthreads();  // previous tile consumers done
        // keys: sf[k][n] = f[b][k][n0+n]
#pragma unroll
        for (int i = 0; i < 16; i++) {
            int e = t + i * 256; int k = e >> 7, nn = e & 127;
            sf[k * PADF + nn] = d_fp[((size_t)b * 32 + k) * 1024 + n0 + nn];
        }
        // values: sv[n][c] = hh[b][c][n0+n]  (float4 over n)
#pragma unroll
        for (int i = 0; i < 16; i++) {
            int e = t + i * 256; int c = e >> 5, n4 = e & 31;
            float4 hv = *(const float4*)(d_hp + ((size_t)b * 128 + c) * 1024 + n0 + n4 * 4);
            sv[(n4 * 4 + 0) * PADV + c] = hv.x;
            sv[(n4 * 4 + 1) * PADV + c] = hv.y;
            sv[(n4 * 4 + 2) * PADV + c] = hv.z;
            sv[(n4 * 4 + 3) * PADV + c] = hv.w;
        }
        __syncthreads();

        // ---- logits GEMM: S[n][m], thread owns 4 n x 8 m ----
        {
            float accS[4][8];
#pragma unroll
            for (int i = 0; i < 4; i++)
#pragma unroll
                for (int j = 0; j < 8; j++) accS[i][j] = 0.f;
#pragma unroll
            for (int k = 0; k < 32; k++) {
                float fr[4], qr[8];
#pragma unroll
                for (int i = 0; i < 4; i++) fr[i] = sf[k * PADF + tyc * 4 + i];
#pragma unroll
                for (int j = 0; j < 8; j++) qr[j] = sg[k * 64 + txm * 8 + j];
#pragma unroll
                for (int i = 0; i < 4; i++)
#pragma unroll
                    for (int j = 0; j < 8; j++) accS[i][j] += fr[i] * qr[j];
            }
#pragma unroll
            for (int i = 0; i < 4; i++) {
                float4 a0 = make_float4(accS[i][0], accS[i][1], accS[i][2], accS[i][3]);
                float4 a1 = make_float4(accS[i][4], accS[i][5], accS[i][6], accS[i][7]);
                *(float4*)(sp + (tyc * 4 + i) * PADP + txm * 8)     = a0;
                *(float4*)(sp + (tyc * 4 + i) * PADP + txm * 8 + 4) = a1;
            }
        }
        __syncthreads();

        // ---- online softmax over n, 4 threads per column msm ----
        float tmax = -3.0e38f;
#pragma unroll
        for (int nn = 0; nn < 32; nn++)
            tmax = fmaxf(tmax, sp[(q * 32 + nn) * PADP + msm]);
        sred[q * 64 + msm] = tmax;
        __syncthreads();
        float tileMax = fmaxf(fmaxf(sred[msm], sred[64 + msm]),
                              fmaxf(sred[128 + msm], sred[192 + msm]));
        float newM = fmaxf(runM, tileMax);
        float corr = __expf(runM - newM);
        if (q == 0) scorr[msm] = corr;
        float psum = 0.f;
#pragma unroll
        for (int nn = 0; nn < 32; nn++) {
            int ix = (q * 32 + nn) * PADP + msm;
            float p = __expf(sp[ix] - newM);
            sp[ix] = p;
            psum += p;
        }
        sred[256 + q * 64 + msm] = psum;
        __syncthreads();
        runL = runL * corr + (sred[256 + msm] + sred[320 + msm] + sred[384 + msm] + sred[448 + msm]);
        runM = newM;

        // ---- PV accumulate: accO[c_i][m_j] += v[n][c] * P[n][m] ----
        {
            float cr[8];
#pragma unroll
            for (int j = 0; j < 8; j++) cr[j] = scorr[txm * 8 + j];
#pragma unroll
            for (int i = 0; i < 4; i++)
#pragma unroll
                for (int j = 0; j < 8; j++) accO[i][j] *= cr[j];
#pragma unroll 2
            for (int n = 0; n < 128; n++) {
                float4 v4 = *(const float4*)(sv + n * PADV + tyc * 4);
                float4 p0 = *(const float4*)(sp + n * PADP + txm * 8);
                float4 p1 = *(const float4*)(sp + n * PADP + txm * 8 + 4);
                float vv[4] = { v4.x, v4.y, v4.z, v4.w };
                float pp[8] = { p0.x, p0.y, p0.z, p0.w, p1.x, p1.y, p1.z, p1.w };
#pragma unroll
                for (int i = 0; i < 4; i++)
#pragma unroll
                    for (int j = 0; j < 8; j++) accO[i][j] += vv[i] * pp[j];
            }
        }
    }

    __syncthreads();
    if (q == 0) sl[msm] = runL;
    __syncthreads();

    float inv[8];
#pragma unroll
    for (int j = 0; j < 8; j++) inv[j] = 1.0f / sl[txm * 8 + j];
#pragma unroll
    for (int i = 0; i < 4; i++) {
        size_t off = ((size_t)b * 128 + tyc * 4 + i) * HW + m0 + txm * 8;
        float4 o0 = make_float4(accO[i][0] * inv[0], accO[i][1] * inv[1],
                                accO[i][2] * inv[2], accO[i][3] * inv[3]);
        float4 o1 = make_float4(accO[i][4] * inv[4], accO[i][5] * inv[5],
                                accO[i][6] * inv[6], accO[i][7] * inv[7]);
        *(float4*)(d_ov + off)     = o0;
        *(float4*)(d_ov + off + 4) = o1;
    }
}

// ---------------- launch ----------------
extern "C" void kernel_launch(void* const* d_in, const int* in_sizes, int n_in,
                              void* d_out, int out_size)
{
    const float* x  = (const float*)d_in[0];
    const float* w1 = (const float*)d_in[1],  *b1 = (const float*)d_in[2],
               *s1 = (const float*)d_in[3],  *t1 = (const float*)d_in[4],
               *m1 = (const float*)d_in[5],  *v1 = (const float*)d_in[6];
    const float* w2 = (const float*)d_in[7],  *b2 = (const float*)d_in[8],
               *s2 = (const float*)d_in[9],  *t2 = (const float*)d_in[10],
               *m2 = (const float*)d_in[11], *v2 = (const float*)d_in[12];
    const float* w3 = (const float*)d_in[13], *b3 = (const float*)d_in[14],
               *s3 = (const float*)d_in[15], *t3 = (const float*)d_in[16],
               *m3 = (const float*)d_in[17], *v3 = (const float*)d_in[18];
    const float* w4 = (const float*)d_in[19], *b4 = (const float*)d_in[20],
               *s4 = (const float*)d_in[21], *t4 = (const float*)d_in[22],
               *m4 = (const float*)d_in[23], *v4 = (const float*)d_in[24];
    const float* gamma = (const float*)d_in[25];
    float* out = (float*)d_out;

    const int attn_smem = (32 * 64 + 32 * PADF + 128 * PADV + 128 * PADP + 512 + 64 + 64) * 4;
    cudaFuncSetAttribute(attn_kernel, cudaFuncAttributeMaxDynamicSharedMemorySize, attn_smem);

    prep_kernel<<<192, 256>>>(w1, b1, s1, t1, m1, v1,
                              w2, b2, s2, t2, m2, v2,
                              w3, b3, s3, t3, m3, v3,
                              w4, b4, s4, t4, m4, v4);

    gemm_kernel<0><<<dim3(32, 3, 8), 256>>>(x, nullptr, nullptr);

    pool_kernel<<<(8 * 160 * 1024 + 255) / 256, 256>>>();

    attn_kernel<<<dim3(64, 8), 256, attn_smem>>>();

    gemm_kernel<1><<<dim3(32, 4, 8), 256>>>(x, out, gamma);
}

// round 4
// speedup vs baseline: 1.6336x; 1.6336x over previous
#include <cuda_runtime.h>
#include <math.h>
#include <stdint.h>

#define HW 4096
#define EPSBN 1e-5f

typedef unsigned long long ull;

// ---------------- f32x2 packed-FP32 helpers (SASS FFMA2 path) ----------------
__device__ __forceinline__ ull fdup(float x) {
    ull d; asm("mov.b64 %0, {%1, %1};" : "=l"(d) : "f"(x)); return d;
}
__device__ __forceinline__ ull fpk(float x, float y) {
    ull d; asm("mov.b64 %0, {%1, %2};" : "=l"(d) : "f"(x), "f"(y)); return d;
}
__device__ __forceinline__ void ffma2(ull& d, ull a, ull b) {
    asm("fma.rn.f32x2 %0, %1, %2, %0;" : "+l"(d) : "l"(a), "l"(b));
}
__device__ __forceinline__ ull fmul2(ull a, ull b) {
    ull d; asm("mul.rn.f32x2 %0, %1, %2;" : "=l"(d) : "l"(a), "l"(b)); return d;
}
__device__ __forceinline__ float2 funp(ull d) {
    float2 f; asm("mov.b64 {%0, %1}, %2;" : "=f"(f.x), "=f"(f.y) : "l"(d)); return f;
}

// ---------------- scratch (static device allocations) ----------------
__device__ float d_wall[192 * 256];                 // folded W for convs 1,2,3 stacked
__device__ float d_ball[192];
__device__ float d_w4f[256 * 128];                  // folded W4
__device__ float d_b4f[256];
__device__ float d_yall[(size_t)8 * 192 * 4096];    // conv1/2/3 outputs (ReLU'd)
__device__ float d_fp[(size_t)8 * 32 * 1024];       // pooled f  [b][k][n]
__device__ float d_hp[(size_t)8 * 1024 * 128];      // pooled hh TRANSPOSED [b][n][c]
__device__ float d_ov[(size_t)8 * 128 * 4096];      // attention output o [b][c][m]

// ---------------- prep: fold BN into conv weights ----------------
__global__ void prep_kernel(
    const float* w1, const float* b1, const float* s1, const float* t1, const float* m1, const float* v1,
    const float* w2, const float* b2, const float* s2, const float* t2, const float* m2, const float* v2,
    const float* w3, const float* b3, const float* s3, const float* t3, const float* m3, const float* v3,
    const float* w4, const float* b4, const float* s4, const float* t4, const float* m4, const float* v4)
{
    int i = blockIdx.x * 256 + threadIdx.x;
    if (i < 192 * 256) {
        int row = i >> 8, c = i & 255;
        const float *w, *s, *v; int oc;
        if (row < 32)      { w = w1; s = s1; v = v1; oc = row; }
        else if (row < 64) { w = w2; s = s2; v = v2; oc = row - 32; }
        else               { w = w3; s = s3; v = v3; oc = row - 64; }
        float sc = s[oc] * rsqrtf(v[oc] + EPSBN);
        d_wall[i] = w[oc * 256 + c] * sc;
    }
    if (i < 256 * 128) {
        int row = i >> 7, c = i & 127;
        float sc = s4[row] * rsqrtf(v4[row] + EPSBN);
        d_w4f[i] = w4[row * 128 + c] * sc;
    }
    if (i < 192) {
        const float *bb, *s, *v, *mm, *tt; int oc;
        if (i < 32)      { bb = b1; s = s1; v = v1; mm = m1; tt = t1; oc = i; }
        else if (i < 64) { bb = b2; s = s2; v = v2; mm = m2; tt = t2; oc = i - 32; }
        else             { bb = b3; s = s3; v = v3; mm = m3; tt = t3; oc = i - 64; }
        float sc = s[oc] * rsqrtf(v[oc] + EPSBN);
        d_ball[i] = (bb[oc] - mm[oc]) * sc + tt[oc];
    }
    if (i < 256) {
        float sc = s4[i] * rsqrtf(v4[i] + EPSBN);
        d_b4f[i] = (b4[i] - m4[i]) * sc + t4[i];
    }
}

// ---------------- conv1x1 GEMM (MODE 0: convs1-3 + ReLU -> d_yall,
//                                MODE 1: conv4 + gamma*(.)+x -> out) ----------------
template <int MODE>
__global__ void gemm_kernel(const float* __restrict__ X, float* __restrict__ Out,
                            const float* __restrict__ gamma_p)
{
    constexpr int M = (MODE == 0) ? 192 : 256;
    constexpr int K = (MODE == 0) ? 256 : 128;
    const float* W    = (MODE == 0) ? d_wall : d_w4f;
    const float* bias = (MODE == 0) ? d_ball : d_b4f;

    const int b  = blockIdx.z;
    const int m0 = blockIdx.y * 64;
    const int n0 = blockIdx.x * 128;
    const float* in = ((MODE == 0) ? X : (const float*)d_ov) + (size_t)b * K * HW;
    float* Obase = (MODE == 0) ? d_yall : Out;

    __shared__ float ws[32][68];
    __shared__ float xs[32][132];

    ull acc[4][4];
#pragma unroll
    for (int i = 0; i < 4; i++)
#pragma unroll
        for (int j = 0; j < 4; j++) acc[i][j] = 0ULL;

    const int t = threadIdx.x;
    const int ty = t >> 4, tx = t & 15;

    for (int k0 = 0; k0 < K; k0 += 32) {
#pragma unroll
        for (int i = 0; i < 8; i++) {
            int e = t + i * 256; int mm = e >> 5, kk = e & 31;
            ws[kk][mm] = W[(m0 + mm) * K + k0 + kk];
        }
#pragma unroll
        for (int i = 0; i < 4; i++) {
            int e = t + i * 256; int kk = e >> 5, p4 = e & 31;
            *(float4*)&xs[kk][p4 * 4] =
                *(const float4*)(in + (size_t)(k0 + kk) * HW + n0 + p4 * 4);
        }
        __syncthreads();
#pragma unroll 8
        for (int kk = 0; kk < 32; kk++) {
            float4 w4 = *(const float4*)&ws[kk][ty * 4];
            ull a0 = fdup(w4.x), a1 = fdup(w4.y), a2 = fdup(w4.z), a3 = fdup(w4.w);
            ulonglong2 x0 = *(const ulonglong2*)&xs[kk][tx * 8];
            ulonglong2 x1 = *(const ulonglong2*)&xs[kk][tx * 8 + 4];
            ull bb[4] = { x0.x, x0.y, x1.x, x1.y };
#pragma unroll
            for (int j = 0; j < 4; j++) {
                ffma2(acc[0][j], a0, bb[j]);
                ffma2(acc[1][j], a1, bb[j]);
                ffma2(acc[2][j], a2, bb[j]);
                ffma2(acc[3][j], a3, bb[j]);
            }
        }
        __syncthreads();
    }

    float gm = (MODE == 1) ? gamma_p[0] : 0.f;
#pragma unroll
    for (int i = 0; i < 4; i++) {
        int r = m0 + ty * 4 + i;
        float bv = bias[r];
        size_t off = ((size_t)b * M + r) * HW + n0 + tx * 8;
        float2 u0 = funp(acc[i][0]), u1 = funp(acc[i][1]);
        float2 u2 = funp(acc[i][2]), u3 = funp(acc[i][3]);
        float4 o0, o1;
        if (MODE == 0) {
            o0.x = fmaxf(u0.x + bv, 0.f); o0.y = fmaxf(u0.y + bv, 0.f);
            o0.z = fmaxf(u1.x + bv, 0.f); o0.w = fmaxf(u1.y + bv, 0.f);
            o1.x = fmaxf(u2.x + bv, 0.f); o1.y = fmaxf(u2.y + bv, 0.f);
            o1.z = fmaxf(u3.x + bv, 0.f); o1.w = fmaxf(u3.y + bv, 0.f);
        } else {
            const float4 r0 = *(const float4*)(X + off);
            const float4 r1 = *(const float4*)(X + off + 4);
            o0.x = gm * (u0.x + bv) + r0.x; o0.y = gm * (u0.y + bv) + r0.y;
            o0.z = gm * (u1.x + bv) + r0.z; o0.w = gm * (u1.y + bv) + r0.w;
            o1.x = gm * (u2.x + bv) + r1.x; o1.y = gm * (u2.y + bv) + r1.y;
            o1.z = gm * (u3.x + bv) + r1.z; o1.w = gm * (u3.y + bv) + r1.w;
        }
        *(float4*)(Obase + off)     = o0;
        *(float4*)(Obase + off + 4) = o1;
    }
}

// ---------------- 2x2 maxpool; hh written TRANSPOSED [b][n][c] ----------------
__global__ void pool_kernel()
{
    int idx = blockIdx.x * 256 + threadIdx.x;
    if (idx >= 8 * 160 * 1024) return;
    int n = idx & 1023;
    int r = (idx >> 10) % 160;
    int b = idx / (160 * 1024);
    int ph = n >> 5, pw = n & 31;
    int sr = (r < 32) ? r : r + 32;   // hpre rows live at 64..191
    const float* base = d_yall + ((size_t)(b * 192 + sr)) * HW + ph * 128 + pw * 2;
    float v = fmaxf(fmaxf(base[0], base[1]), fmaxf(base[64], base[65]));
    if (r < 32) d_fp[((size_t)b * 32 + r) * 1024 + n] = v;
    else        d_hp[((size_t)b * 1024 + n) * 128 + (r - 32)] = v;
}

// ---------------- fused flash-style attention (f32x2, m-tile 128) ----------------
// S[n][m] = sum_k f[n][k]*g[k][m]; softmax over n (1024); o[c][m] = sum_n hh[n][c] P[n][m]
#define PAD 132

__global__ void __launch_bounds__(256) attn_kernel()
{
    extern __shared__ float sm[];
    float* sg    = sm;               // [32][PAD]  queries g
    float* sf    = sg + 32 * PAD;    // [32][PAD]  keys f (k-major)
    float* sv    = sf + 32 * PAD;    // [128][PAD] values [n][c]
    float* sp    = sv + 128 * PAD;   // [128][PAD] logits/probs
    float* sred  = sp + 128 * PAD;   // [0..255] max partials, [256..511] sum partials
    float* scorr = sred + 512;       // [128]
    float* sl    = scorr + 128;      // [128]

    const int b  = blockIdx.y;
    const int m0 = blockIdx.x * 128;
    const int t  = threadIdx.x;

    // q tile: sg[k][m] = g[b][k][m0+m]  (g = yall rows 32..63)
#pragma unroll
    for (int i = 0; i < 4; i++) {
        int idx = t + i * 256; int k = idx >> 5, m4 = idx & 31;
        *(float4*)&sg[k * PAD + m4 * 4] =
            *(const float4*)(d_yall + ((size_t)(b * 192 + 32 + k)) * HW + m0 + m4 * 4);
    }

    const int ty = t >> 4, tx = t & 15;     // GEMM tiles: 8 (n or c) x 8 m per thread
    const int msm = t & 127, q = t >> 7;    // softmax: 2 threads per query column

    ull accO[8][4];
#pragma unroll
    for (int i = 0; i < 8; i++)
#pragma unroll
        for (int j = 0; j < 4; j++) accO[i][j] = 0ULL;
    float runM = -3.0e38f, runL = 0.f;

    for (int n0 = 0; n0 < 1024; n0 += 128) {
        __syncthreads();  // previous tile consumers done
        // keys: sf[k][n] = f[b][k][n0+n]
#pragma unroll
        for (int i = 0; i < 4; i++) {
            int idx = t + i * 256; int k = idx >> 5, n4 = idx & 31;
            *(float4*)&sf[k * PAD + n4 * 4] =
                *(const float4*)(d_fp + ((size_t)b * 32 + k) * 1024 + n0 + n4 * 4);
        }
        // values: sv[n][c] directly from transposed d_hp
#pragma unroll
        for (int i = 0; i < 16; i++) {
            int idx = t + i * 256; int n = idx >> 5, c4 = idx & 31;
            *(float4*)&sv[n * PAD + c4 * 4] =
                *(const float4*)(d_hp + ((size_t)b * 1024 + n0 + n) * 128 + c4 * 4);
        }
        __syncthreads();

        // ---- logits GEMM: S[n][m], thread owns 8 n x 8 m (f32x2 over m) ----
        {
            ull accS[8][4];
#pragma unroll
            for (int i = 0; i < 8; i++)
#pragma unroll
                for (int j = 0; j < 4; j++) accS[i][j] = 0ULL;
#pragma unroll 4
            for (int k = 0; k < 32; k++) {
                float4 f0 = *(const float4*)&sf[k * PAD + ty * 8];
                float4 f1 = *(const float4*)&sf[k * PAD + ty * 8 + 4];
                ull a[8] = { fdup(f0.x), fdup(f0.y), fdup(f0.z), fdup(f0.w),
                             fdup(f1.x), fdup(f1.y), fdup(f1.z), fdup(f1.w) };
                ulonglong2 q0 = *(const ulonglong2*)&sg[k * PAD + tx * 8];
                ulonglong2 q1 = *(const ulonglong2*)&sg[k * PAD + tx * 8 + 4];
                ull bb[4] = { q0.x, q0.y, q1.x, q1.y };
#pragma unroll
                for (int i = 0; i < 8; i++)
#pragma unroll
                    for (int j = 0; j < 4; j++) ffma2(accS[i][j], a[i], bb[j]);
            }
#pragma unroll
            for (int i = 0; i < 8; i++) {
                *(ulonglong2*)&sp[(ty * 8 + i) * PAD + tx * 8]     =
                    make_ulonglong2(accS[i][0], accS[i][1]);
                *(ulonglong2*)&sp[(ty * 8 + i) * PAD + tx * 8 + 4] =
                    make_ulonglong2(accS[i][2], accS[i][3]);
            }
        }
        __syncthreads();

        // ---- online softmax over n, 2 threads per column ----
        float tmax = -3.0e38f;
#pragma unroll
        for (int nn = 0; nn < 64; nn++)
            tmax = fmaxf(tmax, sp[(q * 64 + nn) * PAD + msm]);
        sred[q * 128 + msm] = tmax;
        __syncthreads();
        float tileMax = fmaxf(sred[msm], sred[128 + msm]);
        float newM = fmaxf(runM, tileMax);
        float corr = __expf(runM - newM);
        float psum = 0.f;
#pragma unroll
        for (int nn = 0; nn < 64; nn++) {
            int ix = (q * 64 + nn) * PAD + msm;
            float p = __expf(sp[ix] - newM);
            sp[ix] = p;
            psum += p;
        }
        sred[256 + q * 128 + msm] = psum;
        if (q == 0) scorr[msm] = corr;
        runM = newM;
        __syncthreads();
        runL = runL * corr + sred[256 + msm] + sred[384 + msm];

        // ---- PV accumulate: accO[c][m] += v[n][c] * P[n][m] ----
        {
            ull cr[4];
            float4 c0 = *(const float4*)&scorr[tx * 8];
            float4 c1 = *(const float4*)&scorr[tx * 8 + 4];
            cr[0] = fpk(c0.x, c0.y); cr[1] = fpk(c0.z, c0.w);
            cr[2] = fpk(c1.x, c1.y); cr[3] = fpk(c1.z, c1.w);
#pragma unroll
            for (int i = 0; i < 8; i++)
#pragma unroll
                for (int j = 0; j < 4; j++) accO[i][j] = fmul2(accO[i][j], cr[j]);
#pragma unroll 2
            for (int n = 0; n < 128; n++) {
                float4 v0 = *(const float4*)&sv[n * PAD + ty * 8];
                float4 v1 = *(const float4*)&sv[n * PAD + ty * 8 + 4];
                ull a[8] = { fdup(v0.x), fdup(v0.y), fdup(v0.z), fdup(v0.w),
                             fdup(v1.x), fdup(v1.y), fdup(v1.z), fdup(v1.w) };
                ulonglong2 p0 = *(const ulonglong2*)&sp[n * PAD + tx * 8];
                ulonglong2 p1 = *(const ulonglong2*)&sp[n * PAD + tx * 8 + 4];
                ull pp[4] = { p0.x, p0.y, p1.x, p1.y };
#pragma unroll
                for (int i = 0; i < 8; i++)
#pragma unroll
                    for (int j = 0; j < 4; j++) ffma2(accO[i][j], a[i], pp[j]);
            }
        }
    }

    __syncthreads();
    if (q == 0) sl[msm] = runL;
    __syncthreads();

    ull inv[4];
    {
        float4 l0 = *(const float4*)&sl[tx * 8];
        float4 l1 = *(const float4*)&sl[tx * 8 + 4];
        inv[0] = fpk(1.0f / l0.x, 1.0f / l0.y);
        inv[1] = fpk(1.0f / l0.z, 1.0f / l0.w);
        inv[2] = fpk(1.0f / l1.x, 1.0f / l1.y);
        inv[3] = fpk(1.0f / l1.z, 1.0f / l1.w);
    }
#pragma unroll
    for (int i = 0; i < 8; i++) {
        size_t off = ((size_t)b * 128 + ty * 8 + i) * HW + m0 + tx * 8;
        ull o0 = fmul2(accO[i][0], inv[0]);
        ull o1 = fmul2(accO[i][1], inv[1]);
        ull o2 = fmul2(accO[i][2], inv[2]);
        ull o3 = fmul2(accO[i][3], inv[3]);
        *(ulonglong2*)(d_ov + off)     = make_ulonglong2(o0, o1);
        *(ulonglong2*)(d_ov + off + 4) = make_ulonglong2(o2, o3);
    }
}

// ---------------- launch ----------------
extern "C" void kernel_launch(void* const* d_in, const int* in_sizes, int n_in,
                              void* d_out, int out_size)
{
    const float* x  = (const float*)d_in[0];
    const float* w1 = (const float*)d_in[1],  *b1 = (const float*)d_in[2],
               *s1 = (const float*)d_in[3],  *t1 = (const float*)d_in[4],
               *m1 = (const float*)d_in[5],  *v1 = (const float*)d_in[6];
    const float* w2 = (const float*)d_in[7],  *b2 = (const float*)d_in[8],
               *s2 = (const float*)d_in[9],  *t2 = (const float*)d_in[10],
               *m2 = (const float*)d_in[11], *v2 = (const float*)d_in[12];
    const float* w3 = (const float*)d_in[13], *b3 = (const float*)d_in[14],
               *s3 = (const float*)d_in[15], *t3 = (const float*)d_in[16],
               *m3 = (const float*)d_in[17], *v3 = (const float*)d_in[18];
    const float* w4 = (const float*)d_in[19], *b4 = (const float*)d_in[20],
               *s4 = (const float*)d_in[21], *t4 = (const float*)d_in[22],
               *m4 = (const float*)d_in[23], *v4 = (const float*)d_in[24];
    const float* gamma = (const float*)d_in[25];
    float* out = (float*)d_out;

    const int attn_smem = (320 * PAD + 512 + 128 + 128) * 4;  // 172,032 bytes
    cudaFuncSetAttribute(attn_kernel, cudaFuncAttributeMaxDynamicSharedMemorySize, attn_smem);

    prep_kernel<<<192, 256>>>(w1, b1, s1, t1, m1, v1,
                              w2, b2, s2, t2, m2, v2,
                              w3, b3, s3, t3, m3, v3,
                              w4, b4, s4, t4, m4, v4);

    gemm_kernel<0><<<dim3(32, 3, 8), 256>>>(x, nullptr, nullptr);

    pool_kernel<<<(8 * 160 * 1024 + 255) / 256, 256>>>();

    attn_kernel<<<dim3(32, 8), 256, attn_smem>>>();

    gemm_kernel<1><<<dim3(32, 4, 8), 256>>>(x, out, gamma);
}

// round 5
// speedup vs baseline: 1.8012x; 1.1026x over previous
#include <cuda_runtime.h>
#include <math.h>
#include <stdint.h>

#define HW 4096
#define EPSBN 1e-5f

typedef unsigned long long ull;

// ---------------- f32x2 packed-FP32 helpers (SASS FFMA2 path) ----------------
__device__ __forceinline__ ull fdup(float x) {
    ull d; asm("mov.b64 %0, {%1, %1};" : "=l"(d) : "f"(x)); return d;
}
__device__ __forceinline__ ull fpk(float x, float y) {
    ull d; asm("mov.b64 %0, {%1, %2};" : "=l"(d) : "f"(x), "f"(y)); return d;
}
__device__ __forceinline__ void ffma2(ull& d, ull a, ull b) {
    asm("fma.rn.f32x2 %0, %1, %2, %0;" : "+l"(d) : "l"(a), "l"(b));
}
__device__ __forceinline__ ull fmul2(ull a, ull b) {
    ull d; asm("mul.rn.f32x2 %0, %1, %2;" : "=l"(d) : "l"(a), "l"(b)); return d;
}
__device__ __forceinline__ float2 funp(ull d) {
    float2 f; asm("mov.b64 {%0, %1}, %2;" : "=f"(f.x), "=f"(f.y) : "l"(d)); return f;
}

// ---------------- scratch (static device allocations) ----------------
__device__ float d_wall[192 * 256];                 // folded W for convs 1,2,3 stacked
__device__ float d_ball[192];
__device__ float d_w4t[128 * 256];                  // folded W4 TRANSPOSED [c][r]
__device__ float d_b4f[256];
__device__ float d_yall[(size_t)8 * 192 * 4096];    // only g rows (32..63) used
__device__ float d_fp[(size_t)8 * 32 * 1024];       // pooled f  [b][k][n]
__device__ float d_hp[(size_t)8 * 1024 * 128];      // pooled hh TRANSPOSED [b][n][c]

// ---------------- prep: fold BN into conv weights ----------------
__global__ void prep_kernel(
    const float* w1, const float* b1, const float* s1, const float* t1, const float* m1, const float* v1,
    const float* w2, const float* b2, const float* s2, const float* t2, const float* m2, const float* v2,
    const float* w3, const float* b3, const float* s3, const float* t3, const float* m3, const float* v3,
    const float* w4, const float* b4, const float* s4, const float* t4, const float* m4, const float* v4)
{
    int i = blockIdx.x * 256 + threadIdx.x;
    if (i < 192 * 256) {
        int row = i >> 8, c = i & 255;
        const float *w, *s, *v; int oc;
        if (row < 32)      { w = w1; s = s1; v = v1; oc = row; }
        else if (row < 64) { w = w2; s = s2; v = v2; oc = row - 32; }
        else               { w = w3; s = s3; v = v3; oc = row - 64; }
        float sc = s[oc] * rsqrtf(v[oc] + EPSBN);
        d_wall[i] = w[oc * 256 + c] * sc;
    }
    if (i < 128 * 256) {   // transposed W4: d_w4t[c][r] = w4[r][c] * scale(r)
        int c = i >> 8, r = i & 255;
        float sc = s4[r] * rsqrtf(v4[r] + EPSBN);
        d_w4t[i] = w4[r * 128 + c] * sc;
    }
    if (i < 192) {
        const float *bb, *s, *v, *mm, *tt; int oc;
        if (i < 32)      { bb = b1; s = s1; v = v1; mm = m1; tt = t1; oc = i; }
        else if (i < 64) { bb = b2; s = s2; v = v2; mm = m2; tt = t2; oc = i - 32; }
        else             { bb = b3; s = s3; v = v3; mm = m3; tt = t3; oc = i - 64; }
        float sc = s[oc] * rsqrtf(v[oc] + EPSBN);
        d_ball[i] = (bb[oc] - mm[oc]) * sc + tt[oc];
    }
    if (i < 256) {
        float sc = s4[i] * rsqrtf(v4[i] + EPSBN);
        d_b4f[i] = (b4[i] - m4[i]) * sc + t4[i];
    }
}

// ---------------- conv1x1 GEMM for convs 1-3 + ReLU + fused 2x2 maxpool ----------------
// rows 0..31 -> pooled into d_fp; rows 32..63 -> stored to d_yall (g);
// rows 64..191 -> pooled into d_hp (transposed [b][n][c]).
// Block n-tile of 128 spatial cols == h rows {2*bx, 2*bx+1} -> full 2x2 windows in-block.
__global__ void __launch_bounds__(256) gemm_kernel(const float* __restrict__ X)
{
    const int b  = blockIdx.z;
    const int m0 = blockIdx.y * 64;
    const int bx = blockIdx.x;
    const int n0 = bx * 128;
    const float* in = X + (size_t)b * 256 * HW;

    __shared__ float ws[32][68];
    __shared__ float xs[32][132];

    ull acc[4][4];
#pragma unroll
    for (int i = 0; i < 4; i++)
#pragma unroll
        for (int j = 0; j < 4; j++) acc[i][j] = 0ULL;

    const int t = threadIdx.x;
    const int ty = t >> 4, tx = t & 15;

    for (int k0 = 0; k0 < 256; k0 += 32) {
#pragma unroll
        for (int i = 0; i < 8; i++) {
            int e = t + i * 256; int mm = e >> 5, kk = e & 31;
            ws[kk][mm] = d_wall[(m0 + mm) * 256 + k0 + kk];
        }
#pragma unroll
        for (int i = 0; i < 4; i++) {
            int e = t + i * 256; int kk = e >> 5, p4 = e & 31;
            *(float4*)&xs[kk][p4 * 4] =
                *(const float4*)(in + (size_t)(k0 + kk) * HW + n0 + p4 * 4);
        }
        __syncthreads();
#pragma unroll 8
        for (int kk = 0; kk < 32; kk++) {
            float4 w4 = *(const float4*)&ws[kk][ty * 4];
            ull a0 = fdup(w4.x), a1 = fdup(w4.y), a2 = fdup(w4.z), a3 = fdup(w4.w);
            ulonglong2 x0 = *(const ulonglong2*)&xs[kk][tx * 8];
            ulonglong2 x1 = *(const ulonglong2*)&xs[kk][tx * 8 + 4];
            ull bb[4] = { x0.x, x0.y, x1.x, x1.y };
#pragma unroll
            for (int j = 0; j < 4; j++) {
                ffma2(acc[0][j], a0, bb[j]);
                ffma2(acc[1][j], a1, bb[j]);
                ffma2(acc[2][j], a2, bb[j]);
                ffma2(acc[3][j], a3, bb[j]);
            }
        }
        __syncthreads();
    }

    // relu'd values
    float va[4][8];
    const int r0 = m0 + ty * 4;
#pragma unroll
    for (int i = 0; i < 4; i++) {
        float bv = d_ball[r0 + i];
        float2 u0 = funp(acc[i][0]), u1 = funp(acc[i][1]);
        float2 u2 = funp(acc[i][2]), u3 = funp(acc[i][3]);
        va[i][0] = fmaxf(u0.x + bv, 0.f); va[i][1] = fmaxf(u0.y + bv, 0.f);
        va[i][2] = fmaxf(u1.x + bv, 0.f); va[i][3] = fmaxf(u1.y + bv, 0.f);
        va[i][4] = fmaxf(u2.x + bv, 0.f); va[i][5] = fmaxf(u2.y + bv, 0.f);
        va[i][6] = fmaxf(u3.x + bv, 0.f); va[i][7] = fmaxf(u3.y + bv, 0.f);
    }

    if (r0 >= 32 && r0 < 64) {
        // g rows: store full-resolution to d_yall
#pragma unroll
        for (int i = 0; i < 4; i++) {
            size_t off = ((size_t)b * 192 + r0 + i) * HW + n0 + tx * 8;
            *(float4*)(d_yall + off)     = make_float4(va[i][0], va[i][1], va[i][2], va[i][3]);
            *(float4*)(d_yall + off + 4) = make_float4(va[i][4], va[i][5], va[i][6], va[i][7]);
        }
    } else {
        // 2x2 maxpool: w-pairs in-thread, h-partner at lane tx^8
        float mw[4][4];
#pragma unroll
        for (int i = 0; i < 4; i++)
#pragma unroll
            for (int jj = 0; jj < 4; jj++)
                mw[i][jj] = fmaxf(va[i][2 * jj], va[i][2 * jj + 1]);
#pragma unroll
        for (int i = 0; i < 4; i++)
#pragma unroll
            for (int jj = 0; jj < 4; jj++) {
                float p = __shfl_xor_sync(0xffffffffu, mw[i][jj], 8);
                mw[i][jj] = fmaxf(mw[i][jj], p);
            }
        if (tx < 8) {
            int npb = bx * 32 + tx * 4;
            if (r0 < 32) {
#pragma unroll
                for (int i = 0; i < 4; i++)
                    *(float4*)&d_fp[((size_t)b * 32 + r0 + i) * 1024 + npb] =
                        make_float4(mw[i][0], mw[i][1], mw[i][2], mw[i][3]);
            } else {
                int c0 = r0 - 64;
#pragma unroll
                for (int jj = 0; jj < 4; jj++)
                    *(float4*)&d_hp[((size_t)b * 1024 + npb + jj) * 128 + c0] =
                        make_float4(mw[0][jj], mw[1][jj], mw[2][jj], mw[3][jj]);
            }
        }
    }
}

// ---------------- fused flash attention + conv4 + gamma*out + x ----------------
// S[n][m] = sum_k f[n][k]*g[k][m]; softmax over n (1024); o[c][m] = sum_n hh[n][c] P[n][m];
// out[r][m] = gamma*(sum_c w4t[c][r]*o[c][m] + b4) + x[r][m]
#define PAD 132

__global__ void __launch_bounds__(256) attn_kernel(const float* __restrict__ X,
                                                   float* __restrict__ Out,
                                                   const float* __restrict__ gamma_p)
{
    extern __shared__ float sm[];
    float* sg    = sm;               // [32][PAD]  queries g   (reused as ws2 in epilogue)
    float* sf    = sg + 32 * PAD;    // [32][PAD]  keys f (k-major)
    float* sv    = sf + 32 * PAD;    // [128][PAD] values [n][c]
    float* sp    = sv + 128 * PAD;   // [128][PAD] logits/probs, then normalized o
    float* sred  = sp + 128 * PAD;   // [0..255] max partials, [256..511] sum partials
    float* scorr = sred + 512;       // [128]
    float* sl    = scorr + 128;      // [128]
    float* ws2   = sm;               // [32][264] W4^T chunk (overlaps sg+sf: 8448 floats)

    const int b  = blockIdx.y;
    const int m0 = blockIdx.x * 128;
    const int t  = threadIdx.x;

    // q tile: sg[k][m] = g[b][k][m0+m]  (g = yall rows 32..63)
#pragma unroll
    for (int i = 0; i < 4; i++) {
        int idx = t + i * 256; int k = idx >> 5, m4 = idx & 31;
        *(float4*)&sg[k * PAD + m4 * 4] =
            *(const float4*)(d_yall + ((size_t)(b * 192 + 32 + k)) * HW + m0 + m4 * 4);
    }

    const int ty = t >> 4, tx = t & 15;     // GEMM tiles: 8 (n or c) x 8 m per thread
    const int msm = t & 127, q = t >> 7;    // softmax: 2 threads per query column

    ull accO[8][4];
#pragma unroll
    for (int i = 0; i < 8; i++)
#pragma unroll
        for (int j = 0; j < 4; j++) accO[i][j] = 0ULL;
    float runM = -3.0e38f, runL = 0.f;

    for (int n0 = 0; n0 < 1024; n0 += 128) {
        __syncthreads();  // previous tile consumers done
        // keys: sf[k][n] = f[b][k][n0+n]
#pragma unroll
        for (int i = 0; i < 4; i++) {
            int idx = t + i * 256; int k = idx >> 5, n4 = idx & 31;
            *(float4*)&sf[k * PAD + n4 * 4] =
                *(const float4*)(d_fp + ((size_t)b * 32 + k) * 1024 + n0 + n4 * 4);
        }
        // values: sv[n][c] directly from transposed d_hp
#pragma unroll
        for (int i = 0; i < 16; i++) {
            int idx = t + i * 256; int n = idx >> 5, c4 = idx & 31;
            *(float4*)&sv[n * PAD + c4 * 4] =
                *(const float4*)(d_hp + ((size_t)b * 1024 + n0 + n) * 128 + c4 * 4);
        }
        __syncthreads();

        // ---- logits GEMM: S[n][m], thread owns 8 n x 8 m (f32x2 over m) ----
        {
            ull accS[8][4];
#pragma unroll
            for (int i = 0; i < 8; i++)
#pragma unroll
                for (int j = 0; j < 4; j++) accS[i][j] = 0ULL;
#pragma unroll 4
            for (int k = 0; k < 32; k++) {
                float4 f0 = *(const float4*)&sf[k * PAD + ty * 8];
                float4 f1 = *(const float4*)&sf[k * PAD + ty * 8 + 4];
                ull a[8] = { fdup(f0.x), fdup(f0.y), fdup(f0.z), fdup(f0.w),
                             fdup(f1.x), fdup(f1.y), fdup(f1.z), fdup(f1.w) };
                ulonglong2 q0 = *(const ulonglong2*)&sg[k * PAD + tx * 8];
                ulonglong2 q1 = *(const ulonglong2*)&sg[k * PAD + tx * 8 + 4];
                ull bb[4] = { q0.x, q0.y, q1.x, q1.y };
#pragma unroll
                for (int i = 0; i < 8; i++)
#pragma unroll
                    for (int j = 0; j < 4; j++) ffma2(accS[i][j], a[i], bb[j]);
            }
#pragma unroll
            for (int i = 0; i < 8; i++) {
                *(ulonglong2*)&sp[(ty * 8 + i) * PAD + tx * 8]     =
                    make_ulonglong2(accS[i][0], accS[i][1]);
                *(ulonglong2*)&sp[(ty * 8 + i) * PAD + tx * 8 + 4] =
                    make_ulonglong2(accS[i][2], accS[i][3]);
            }
        }
        __syncthreads();

        // ---- online softmax over n, 2 threads per column ----
        float tmax = -3.0e38f;
#pragma unroll
        for (int nn = 0; nn < 64; nn++)
            tmax = fmaxf(tmax, sp[(q * 64 + nn) * PAD + msm]);
        sred[q * 128 + msm] = tmax;
        __syncthreads();
        float tileMax = fmaxf(sred[msm], sred[128 + msm]);
        float newM = fmaxf(runM, tileMax);
        float corr = __expf(runM - newM);
        float psum = 0.f;
#pragma unroll
        for (int nn = 0; nn < 64; nn++) {
            int ix = (q * 64 + nn) * PAD + msm;
            float p = __expf(sp[ix] - newM);
            sp[ix] = p;
            psum += p;
        }
        sred[256 + q * 128 + msm] = psum;
        if (q == 0) scorr[msm] = corr;
        runM = newM;
        __syncthreads();
        runL = runL * corr + sred[256 + msm] + sred[384 + msm];

        // ---- PV accumulate: accO[c][m] += v[n][c] * P[n][m] ----
        {
            ull cr[4];
            float4 c0 = *(const float4*)&scorr[tx * 8];
            float4 c1 = *(const float4*)&scorr[tx * 8 + 4];
            cr[0] = fpk(c0.x, c0.y); cr[1] = fpk(c0.z, c0.w);
            cr[2] = fpk(c1.x, c1.y); cr[3] = fpk(c1.z, c1.w);
#pragma unroll
            for (int i = 0; i < 8; i++)
#pragma unroll
                for (int j = 0; j < 4; j++) accO[i][j] = fmul2(accO[i][j], cr[j]);
#pragma unroll 2
            for (int n = 0; n < 128; n++) {
                float4 v0 = *(const float4*)&sv[n * PAD + ty * 8];
                float4 v1 = *(const float4*)&sv[n * PAD + ty * 8 + 4];
                ull a[8] = { fdup(v0.x), fdup(v0.y), fdup(v0.z), fdup(v0.w),
                             fdup(v1.x), fdup(v1.y), fdup(v1.z), fdup(v1.w) };
                ulonglong2 p0 = *(const ulonglong2*)&sp[n * PAD + tx * 8];
                ulonglong2 p1 = *(const ulonglong2*)&sp[n * PAD + tx * 8 + 4];
                ull pp[4] = { p0.x, p0.y, p1.x, p1.y };
#pragma unroll
                for (int i = 0; i < 8; i++)
#pragma unroll
                    for (int j = 0; j < 4; j++) ffma2(accO[i][j], a[i], pp[j]);
            }
        }
    }

    __syncthreads();
    if (q == 0) sl[msm] = runL;
    __syncthreads();

    // normalize o and park it in sp[c][m]
    {
        ull inv[4];
        float4 l0 = *(const float4*)&sl[tx * 8];
        float4 l1 = *(const float4*)&sl[tx * 8 + 4];
        inv[0] = fpk(1.0f / l0.x, 1.0f / l0.y);
        inv[1] = fpk(1.0f / l0.z, 1.0f / l0.w);
        inv[2] = fpk(1.0f / l1.x, 1.0f / l1.y);
        inv[3] = fpk(1.0f / l1.z, 1.0f / l1.w);
#pragma unroll
        for (int i = 0; i < 8; i++) {
            ull o0 = fmul2(accO[i][0], inv[0]);
            ull o1 = fmul2(accO[i][1], inv[1]);
            ull o2 = fmul2(accO[i][2], inv[2]);
            ull o3 = fmul2(accO[i][3], inv[3]);
            *(ulonglong2*)&sp[(ty * 8 + i) * PAD + tx * 8]     = make_ulonglong2(o0, o1);
            *(ulonglong2*)&sp[(ty * 8 + i) * PAD + tx * 8 + 4] = make_ulonglong2(o2, o3);
        }
    }
    const float gm = gamma_p[0];
    __syncthreads();   // sp(o) visible; sg/sf now dead -> ws2 reuse safe

    // ---- fused conv4: out[r][m] = gm*(sum_c w4t[c][r]*o[c][m] + b4[r]) + x[r][m] ----
    for (int rp = 0; rp < 2; rp++) {
        ull accE[8][4];
#pragma unroll
        for (int i = 0; i < 8; i++)
#pragma unroll
            for (int j = 0; j < 4; j++) accE[i][j] = 0ULL;

        for (int cc0 = 0; cc0 < 128; cc0 += 32) {
            // stage W4^T chunk: ws2[cl][rl] = w4t[cc0+cl][rp*128+rl]
#pragma unroll
            for (int i2 = 0; i2 < 16; i2++) {
                int e = t + i2 * 256;           // 0..4095
                int rl = e & 127, cl = e >> 7;  // coalesced LDG, conflict-free STS
                ws2[cl * 264 + rl] = d_w4t[(cc0 + cl) * 256 + rp * 128 + rl];
            }
            __syncthreads();
#pragma unroll 4
            for (int cl = 0; cl < 32; cl++) {
                float4 w0 = *(const float4*)&ws2[cl * 264 + ty * 8];
                float4 w1 = *(const float4*)&ws2[cl * 264 + ty * 8 + 4];
                ull a[8] = { fdup(w0.x), fdup(w0.y), fdup(w0.z), fdup(w0.w),
                             fdup(w1.x), fdup(w1.y), fdup(w1.z), fdup(w1.w) };
                ulonglong2 p0 = *(const ulonglong2*)&sp[(cc0 + cl) * PAD + tx * 8];
                ulonglong2 p1 = *(const ulonglong2*)&sp[(cc0 + cl) * PAD + tx * 8 + 4];
                ull bb[4] = { p0.x, p0.y, p1.x, p1.y };
#pragma unroll
                for (int i = 0; i < 8; i++)
#pragma unroll
                    for (int j = 0; j < 4; j++) ffma2(accE[i][j], a[i], bb[j]);
            }
            __syncthreads();
        }

#pragma unroll
        for (int i = 0; i < 8; i++) {
            int r = rp * 128 + ty * 8 + i;
            float bv = d_b4f[r];
            size_t off = ((size_t)b * 256 + r) * HW + m0 + tx * 8;
            float2 u0 = funp(accE[i][0]), u1 = funp(accE[i][1]);
            float2 u2 = funp(accE[i][2]), u3 = funp(accE[i][3]);
            const float4 x0 = *(const float4*)(X + off);
            const float4 x1 = *(const float4*)(X + off + 4);
            float4 o0, o1;
            o0.x = gm * (u0.x + bv) + x0.x; o0.y = gm * (u0.y + bv) + x0.y;
            o0.z = gm * (u1.x + bv) + x0.z; o0.w = gm * (u1.y + bv) + x0.w;
            o1.x = gm * (u2.x + bv) + x1.x; o1.y = gm * (u2.y + bv) + x1.y;
            o1.z = gm * (u3.x + bv) + x1.z; o1.w = gm * (u3.y + bv) + x1.w;
            *(float4*)(Out + off)     = o0;
            *(float4*)(Out + off + 4) = o1;
        }
    }
}

// ---------------- launch ----------------
extern "C" void kernel_launch(void* const* d_in, const int* in_sizes, int n_in,
                              void* d_out, int out_size)
{
    const float* x  = (const float*)d_in[0];
    const float* w1 = (const float*)d_in[1],  *b1 = (const float*)d_in[2],
               *s1 = (const float*)d_in[3],  *t1 = (const float*)d_in[4],
               *m1 = (const float*)d_in[5],  *v1 = (const float*)d_in[6];
    const float* w2 = (const float*)d_in[7],  *b2 = (const float*)d_in[8],
               *s2 = (const float*)d_in[9],  *t2 = (const float*)d_in[10],
               *m2 = (const float*)d_in[11], *v2 = (const float*)d_in[12];
    const float* w3 = (const float*)d_in[13], *b3 = (const float*)d_in[14],
               *s3 = (const float*)d_in[15], *t3 = (const float*)d_in[16],
               *m3 = (const float*)d_in[17], *v3 = (const float*)d_in[18];
    const float* w4 = (const float*)d_in[19], *b4 = (const float*)d_in[20],
               *s4 = (const float*)d_in[21], *t4 = (const float*)d_in[22],
               *m4 = (const float*)d_in[23], *v4 = (const float*)d_in[24];
    const float* gamma = (const float*)d_in[25];
    float* out = (float*)d_out;

    const int attn_smem = (320 * PAD + 512 + 128 + 128) * 4;  // 172,032 bytes
    cudaFuncSetAttribute(attn_kernel, cudaFuncAttributeMaxDynamicSharedMemorySize, attn_smem);

    prep_kernel<<<192, 256>>>(w1, b1, s1, t1, m1, v1,
                              w2, b2, s2, t2, m2, v2,
                              w3, b3, s3, t3, m3, v3,
                              w4, b4, s4, t4, m4, v4);

    gemm_kernel<<<dim3(32, 3, 8), 256>>>(x);

    attn_kernel<<<dim3(32, 8), 256, attn_smem>>>(x, out, gamma);
}